// round 1
// baseline (speedup 1.0000x reference)
#include <cuda_runtime.h>

#define TPB 256
#define NMAX 32768

__device__ int g_cnt[NMAX];

// shared-memory float offsets
#define OFF_W1   0        // [4][17][32] = 2176
#define OFF_B1   2176     // [4][32]     = 128
#define OFF_W2   2304     // [4][32][32] = 4096
#define OFF_B2   6400     // 128
#define OFF_W300 6528     // [32][64] = 2048
#define OFF_B300 8576     // 64
#define OFF_W301 8640     // 2048
#define OFF_B301 10688    // 64
#define OFF_W310 10752    // 2048
#define OFF_B310 12800    // 64
#define OFF_W311 12864    // [32][192] = 6144
#define OFF_B311 19008    // 192
#define OFF_H2   19200    // [4][32][TPB]
#define SMEM_FLOATS (19200 + 4*32*TPB)
#define SMEM_BYTES  (SMEM_FLOATS * 4)

template<int N4>
__device__ __forceinline__ void axpy(float* acc, float x, const float* row){
    const float4* r4 = reinterpret_cast<const float4*>(row);
#pragma unroll
    for (int q = 0; q < N4; q++){
        float4 v = r4[q];
        acc[4*q+0] += x * v.x;
        acc[4*q+1] += x * v.y;
        acc[4*q+2] += x * v.z;
        acc[4*q+3] += x * v.w;
    }
}

__global__ void __launch_bounds__(TPB)
zero_kernel(float* __restrict__ out, int total, int N){
    int i = blockIdx.x * TPB + threadIdx.x;
    if (i < total) out[i] = 0.f;
    if (i < N) g_cnt[i] = 0;
}

__global__ void __launch_bounds__(TPB)
edge_kernel(const int* __restrict__ src, const int* __restrict__ dst,
            const float* __restrict__ feat0, const float* __restrict__ feat1,
            const float* __restrict__ wemb,  const float* __restrict__ radial,
            const float* __restrict__ B00g,  const float* __restrict__ B01g,
            const float* __restrict__ B10g,  const float* __restrict__ B11g,
            const float* __restrict__ W1,  const float* __restrict__ b1,
            const float* __restrict__ W2,  const float* __restrict__ b2,
            const float* __restrict__ W300, const float* __restrict__ b300,
            const float* __restrict__ W301, const float* __restrict__ b301,
            const float* __restrict__ W310, const float* __restrict__ b310,
            const float* __restrict__ W311, const float* __restrict__ b311,
            float* __restrict__ out, int E)
{
    extern __shared__ float sm[];
    const int tid = threadIdx.x;

    // ---- cooperative weight staging ----
#pragma unroll 1
    for (int i = tid; i < 2176; i += TPB) sm[OFF_W1+i]   = W1[i];
#pragma unroll 1
    for (int i = tid; i < 128;  i += TPB) sm[OFF_B1+i]   = b1[i];
#pragma unroll 1
    for (int i = tid; i < 4096; i += TPB) sm[OFF_W2+i]   = W2[i];
#pragma unroll 1
    for (int i = tid; i < 128;  i += TPB) sm[OFF_B2+i]   = b2[i];
#pragma unroll 1
    for (int i = tid; i < 2048; i += TPB) sm[OFF_W300+i] = W300[i];
#pragma unroll 1
    for (int i = tid; i < 64;   i += TPB) sm[OFF_B300+i] = b300[i];
#pragma unroll 1
    for (int i = tid; i < 2048; i += TPB) sm[OFF_W301+i] = W301[i];
#pragma unroll 1
    for (int i = tid; i < 64;   i += TPB) sm[OFF_B301+i] = b301[i];
#pragma unroll 1
    for (int i = tid; i < 2048; i += TPB) sm[OFF_W310+i] = W310[i];
#pragma unroll 1
    for (int i = tid; i < 64;   i += TPB) sm[OFF_B310+i] = b310[i];
#pragma unroll 1
    for (int i = tid; i < 6144; i += TPB) sm[OFF_W311+i] = W311[i];
#pragma unroll 1
    for (int i = tid; i < 192;  i += TPB) sm[OFF_B311+i] = b311[i];

    const int e = blockIdx.x * TPB + tid;
    const bool active = (e < E);

    // ---- per-edge input loads (overlap with staging, before sync) ----
    float ef[17];
    float fs0[8];
    float fs1[24];        // [i][n]
    int s = 0, d = 0;
    float b00 = 0.f, B01r[3] = {0,0,0}, B10r[3] = {0,0,0};
    if (active){
        s = src[e]; d = dst[e];
        const float4* w4 = reinterpret_cast<const float4*>(wemb + (size_t)e * 16);
        float4 a = w4[0], b = w4[1], c = w4[2], dd = w4[3];
        ef[0]=a.x;  ef[1]=a.y;  ef[2]=a.z;  ef[3]=a.w;
        ef[4]=b.x;  ef[5]=b.y;  ef[6]=b.z;  ef[7]=b.w;
        ef[8]=c.x;  ef[9]=c.y;  ef[10]=c.z; ef[11]=c.w;
        ef[12]=dd.x; ef[13]=dd.y; ef[14]=dd.z; ef[15]=dd.w;
        ef[16] = radial[e];
        const float4* f04 = reinterpret_cast<const float4*>(feat0 + (size_t)s * 8);
        float4 p = f04[0], q = f04[1];
        fs0[0]=p.x; fs0[1]=p.y; fs0[2]=p.z; fs0[3]=p.w;
        fs0[4]=q.x; fs0[5]=q.y; fs0[6]=q.z; fs0[7]=q.w;
        const float4* f14 = reinterpret_cast<const float4*>(feat1 + (size_t)s * 24);
#pragma unroll
        for (int t = 0; t < 6; t++){
            float4 v = f14[t];
            fs1[4*t+0]=v.x; fs1[4*t+1]=v.y; fs1[4*t+2]=v.z; fs1[4*t+3]=v.w;
        }
        b00 = B00g[e];
#pragma unroll
        for (int m = 0; m < 3; m++){ B01r[m] = B01g[(size_t)e*3+m]; B10r[m] = B10g[(size_t)e*3+m]; }
    }
    __syncthreads();

    if (!active) return;

    // ---- phase 1: four radial MLPs, h2 -> shared (k-major, conflict-free) ----
#pragma unroll 1
    for (int p = 0; p < 4; p++){
        float h[32];
        const float* bp = sm + OFF_B1 + p*32;
#pragma unroll
        for (int k = 0; k < 32; k++) h[k] = bp[k];
        const float* w1p = sm + OFF_W1 + p*544;
#pragma unroll
        for (int j = 0; j < 17; j++) axpy<8>(h, ef[j], w1p + j*32);
#pragma unroll
        for (int k = 0; k < 32; k++) h[k] = fmaxf(h[k], 0.f);

        float h2[32];
        const float* b2p = sm + OFF_B2 + p*32;
#pragma unroll
        for (int k = 0; k < 32; k++) h2[k] = b2p[k];
        const float* w2p = sm + OFF_W2 + p*1024;
#pragma unroll
        for (int j = 0; j < 32; j++) axpy<8>(h2, h[j], w2p + j*32);

        float* hs = sm + OFF_H2 + p*32*TPB + tid;
#pragma unroll
        for (int k = 0; k < 32; k++) hs[k*TPB] = fmaxf(h2[k], 0.f);
    }

    atomicAdd(&g_cnt[d], 1);

    // precontract basis_10 with fs1: g1[i] = sum_n B10[n] * fs1[i][n]
    float g1[8];
#pragma unroll
    for (int i = 0; i < 8; i++)
        g1[i] = B10r[0]*fs1[i*3+0] + B10r[1]*fs1[i*3+1] + B10r[2]*fs1[i*3+2];

    float* outd = out + (size_t)d * 32;
    const float* h0p = sm + OFF_H2 + 0*32*TPB + tid;
    const float* h2p = sm + OFF_H2 + 2*32*TPB + tid;

    // ---- msg0: pairs 0-0 and 1-0 ----
#pragma unroll 1
    for (int o = 0; o < 8; o++){
        float r0[8], r2[8];
        const float* bb0 = sm + OFF_B300 + o*8;
        const float* bb2 = sm + OFF_B310 + o*8;
#pragma unroll
        for (int i = 0; i < 8; i++){ r0[i] = bb0[i]; r2[i] = bb2[i]; }
#pragma unroll 1
        for (int k = 0; k < 32; k++){
            float a0 = h0p[k*TPB];
            float a2 = h2p[k*TPB];
            axpy<2>(r0, a0, sm + OFF_W300 + k*64 + o*8);
            axpy<2>(r2, a2, sm + OFF_W310 + k*64 + o*8);
        }
        float m0 = 0.f, m2 = 0.f;
#pragma unroll
        for (int i = 0; i < 8; i++){ m0 += r0[i]*fs0[i]; m2 += r2[i]*g1[i]; }
        atomicAdd(outd + o*4, b00*m0 + m2);
    }

    // ---- msg1: pairs 0-1 and 1-1 ----
    float B11r[27];
#pragma unroll
    for (int j = 0; j < 27; j++) B11r[j] = B11g[(size_t)e*27 + j];

    const float* h1p = sm + OFF_H2 + 1*32*TPB + tid;
    const float* h3p = sm + OFF_H2 + 3*32*TPB + tid;

#pragma unroll 1
    for (int o = 0; o < 8; o++){
        float r1[8], r3[24];
        const float* bb1 = sm + OFF_B301 + o*8;
        const float* bb3 = sm + OFF_B311 + o*24;
#pragma unroll
        for (int i = 0; i < 8; i++) r1[i] = bb1[i];
#pragma unroll
        for (int j = 0; j < 24; j++) r3[j] = bb3[j];
#pragma unroll 1
        for (int k = 0; k < 32; k++){
            float a1 = h1p[k*TPB];
            float a3 = h3p[k*TPB];
            axpy<2>(r1, a1, sm + OFF_W301 + k*64  + o*8);
            axpy<6>(r3, a3, sm + OFF_W311 + k*192 + o*24);
        }
        float t = 0.f;
#pragma unroll
        for (int i = 0; i < 8; i++) t += r1[i]*fs0[i];

        float S[9];   // S[n*3+f] = sum_i r3[i*3+f] * fs1[i*3+n]
#pragma unroll
        for (int q = 0; q < 9; q++) S[q] = 0.f;
#pragma unroll
        for (int i = 0; i < 8; i++){
#pragma unroll
            for (int f = 0; f < 3; f++){
                float rv = r3[i*3+f];
                S[0*3+f] += rv * fs1[i*3+0];
                S[1*3+f] += rv * fs1[i*3+1];
                S[2*3+f] += rv * fs1[i*3+2];
            }
        }
#pragma unroll
        for (int m = 0; m < 3; m++){
            float acc = B01r[m] * t;
#pragma unroll
            for (int n = 0; n < 3; n++)
#pragma unroll
                for (int f = 0; f < 3; f++)
                    acc += B11r[m*9+n*3+f] * S[n*3+f];
            atomicAdd(outd + o*4 + 1 + m, acc);
        }
    }
}

__global__ void __launch_bounds__(TPB)
finalize_kernel(const float* __restrict__ feat0, const float* __restrict__ feat1,
                const float* __restrict__ ws0, const float* __restrict__ ws1,
                float* __restrict__ out, int N)
{
    int n = blockIdx.x * TPB + threadIdx.x;
    if (n >= N) return;
    int c = g_cnt[n];
    float inv = 1.0f / (float)(c > 1 ? c : 1);
    float sf  = (c > 0) ? 1.0f : 0.0f;

    float f0[8], f1[24];
#pragma unroll
    for (int i = 0; i < 8; i++)  f0[i] = feat0[(size_t)n*8 + i] * sf;
#pragma unroll
    for (int j = 0; j < 24; j++) f1[j] = feat1[(size_t)n*24 + j] * sf;

#pragma unroll
    for (int o = 0; o < 8; o++){
        float a0 = 0.f, a1x = 0.f, a1y = 0.f, a1z = 0.f;
#pragma unroll
        for (int i = 0; i < 8; i++){
            float w0 = ws0[o*8+i];
            float w1 = ws1[o*8+i];
            a0  += w0 * f0[i];
            a1x += w1 * f1[i*3+0];
            a1y += w1 * f1[i*3+1];
            a1z += w1 * f1[i*3+2];
        }
        size_t base = (size_t)n*32 + o*4;
        out[base+0] = out[base+0]*inv + a0;
        out[base+1] = out[base+1]*inv + a1x;
        out[base+2] = out[base+2]*inv + a1y;
        out[base+3] = out[base+3]*inv + a1z;
    }
}

extern "C" void kernel_launch(void* const* d_in, const int* in_sizes, int n_in,
                              void* d_out, int out_size)
{
    const int*   src    = (const int*)  d_in[0];
    const int*   dst    = (const int*)  d_in[1];
    const float* feat0  = (const float*)d_in[2];
    const float* feat1  = (const float*)d_in[3];
    const float* wemb   = (const float*)d_in[4];
    const float* radial = (const float*)d_in[5];
    const float* B00    = (const float*)d_in[6];
    const float* B01    = (const float*)d_in[7];
    const float* B10    = (const float*)d_in[8];
    const float* B11    = (const float*)d_in[9];
    const float* W1     = (const float*)d_in[10];
    const float* b1     = (const float*)d_in[11];
    const float* W2     = (const float*)d_in[12];
    const float* b2     = (const float*)d_in[13];
    const float* W300   = (const float*)d_in[14];
    const float* b300   = (const float*)d_in[15];
    const float* W301   = (const float*)d_in[16];
    const float* b301   = (const float*)d_in[17];
    const float* W310   = (const float*)d_in[18];
    const float* b310   = (const float*)d_in[19];
    const float* W311   = (const float*)d_in[20];
    const float* b311   = (const float*)d_in[21];
    const float* ws0    = (const float*)d_in[22];
    const float* ws1    = (const float*)d_in[23];

    const int E = in_sizes[0];
    const int N = in_sizes[2] / 8;
    float* out = (float*)d_out;

    cudaFuncSetAttribute(edge_kernel,
                         cudaFuncAttributeMaxDynamicSharedMemorySize, SMEM_BYTES);

    int total = N * 32;
    zero_kernel<<<(total + TPB - 1) / TPB, TPB>>>(out, total, N);

    edge_kernel<<<(E + TPB - 1) / TPB, TPB, SMEM_BYTES>>>(
        src, dst, feat0, feat1, wemb, radial,
        B00, B01, B10, B11,
        W1, b1, W2, b2,
        W300, b300, W301, b301, W310, b310, W311, b311,
        out, E);

    finalize_kernel<<<(N + TPB - 1) / TPB, TPB>>>(feat0, feat1, ws0, ws1, out, N);
}

// round 2
// speedup vs baseline: 1.5641x; 1.5641x over previous
#include <cuda_runtime.h>
#include <cstdint>

#define TPB 256
#define NMAX 32768
__device__ int g_cnt[NMAX];

#define TILE_E 128
#define PITCH 36
#define RPITCH 65

// shared float-word offsets
#define OW1   0            // 4*32*36  tf32 (bit patterns in float)
#define OB1   4608         // 128 f32
#define OW2   4736         // 4*32*36
#define OB2   9344         // 128
#define OW3   9472         // 384*36
#define OB3   23296        // 384
#define OEF   23680        // 128*36 tf32
#define OH    28288        // 128*36 tf32
#define ORB   23680        // Rbuf aliases EF+H: 128*65 f32
#define OH2   32896        // 4*128*36 tf32
#define SMEM_WORDS 51328
#define SMEM_BYTES (SMEM_WORDS*4)

__device__ __forceinline__ float f2tf(float f){
    uint32_t u; asm("cvt.rna.tf32.f32 %0, %1;" : "=r"(u) : "f"(f));
    return __uint_as_float(u);
}

__device__ __forceinline__ void mma8(float* d, const uint32_t* a, const uint32_t* b){
    asm volatile("mma.sync.aligned.m16n8k8.row.col.f32.tf32.tf32.f32 "
        "{%0,%1,%2,%3}, {%4,%5,%6,%7}, {%8,%9}, {%0,%1,%2,%3};"
        : "+f"(d[0]), "+f"(d[1]), "+f"(d[2]), "+f"(d[3])
        : "r"(a[0]), "r"(a[1]), "r"(a[2]), "r"(a[3]), "r"(b[0]), "r"(b[1]));
}

// A-fragment load (m16 x k8, tf32) from row-major [row][PITCH]
__device__ __forceinline__ void lda(uint32_t* a, const float* A, int r0, int k0, int q, int t){
    a[0] = __float_as_uint(A[(r0+q)*PITCH   + k0 + t]);
    a[1] = __float_as_uint(A[(r0+q+8)*PITCH + k0 + t]);
    a[2] = __float_as_uint(A[(r0+q)*PITCH   + k0 + 4 + t]);
    a[3] = __float_as_uint(A[(r0+q+8)*PITCH + k0 + 4 + t]);
}
// B-fragment load (k8 x n8) from [n][PITCH] (k-contiguous = col-major k x n)
__device__ __forceinline__ void ldb(uint32_t* b, const float* W, int n0, int k0, int q, int t){
    b[0] = __float_as_uint(W[(n0+q)*PITCH + k0 + t]);
    b[1] = __float_as_uint(W[(n0+q)*PITCH + k0 + 4 + t]);
}

// GEMM3 chunk: [128 x 32] @ [32 x NT*8] -> Rbuf (f32, +bias)
template<int NT>
__device__ __forceinline__ void gemm3_chunk(float* sb, int p, int g0, int r0, int q, int t){
    float d[NT][4] = {};
    const float* A  = sb + OH2 + p*128*PITCH;
    const float* WB = sb + OW3 + g0*PITCH;
#pragma unroll
    for (int k0 = 0; k0 < 32; k0 += 8){
        uint32_t a[4]; lda(a, A, r0, k0, q, t);
#pragma unroll
        for (int nt = 0; nt < NT; nt++){
            uint32_t b[2]; ldb(b, WB, nt*8, k0, q, t);
            mma8(d[nt], a, b);
        }
    }
    float* R = sb + ORB;
    const float* bia = sb + OB3 + g0;
#pragma unroll
    for (int nt = 0; nt < NT; nt++){
        int c0 = nt*8 + t*2;
        R[(r0+q)*RPITCH   + c0]   = d[nt][0] + bia[c0];
        R[(r0+q)*RPITCH   + c0+1] = d[nt][1] + bia[c0+1];
        R[(r0+q+8)*RPITCH + c0]   = d[nt][2] + bia[c0];
        R[(r0+q+8)*RPITCH + c0+1] = d[nt][3] + bia[c0+1];
    }
}

__global__ void __launch_bounds__(TPB)
zero_kernel(float* __restrict__ out, int total, int N){
    int i = blockIdx.x * TPB + threadIdx.x;
    if (i < total) out[i] = 0.f;
    if (i < N) g_cnt[i] = 0;
}

__global__ void __launch_bounds__(TPB, 1)
edge_kernel(const int* __restrict__ src, const int* __restrict__ dst,
            const float* __restrict__ feat0, const float* __restrict__ feat1,
            const float* __restrict__ wemb,  const float* __restrict__ radial,
            const float* __restrict__ B00g,  const float* __restrict__ B01g,
            const float* __restrict__ B10g,  const float* __restrict__ B11g,
            const float* __restrict__ W1,  const float* __restrict__ b1,
            const float* __restrict__ W2,  const float* __restrict__ b2,
            const float* __restrict__ W300, const float* __restrict__ b300,
            const float* __restrict__ W301, const float* __restrict__ b301,
            const float* __restrict__ W310, const float* __restrict__ b310,
            const float* __restrict__ W311, const float* __restrict__ b311,
            float* __restrict__ out, int E, int ntiles)
{
    extern __shared__ float sb[];
    const int tid  = threadIdx.x;
    const int lane = tid & 31;
    const int wid  = tid >> 5;
    const int q = lane >> 2, t = lane & 3;
    const int r0 = wid * 16;

    // ---- stage weights once per block (tf32, transposed to [n][PITCH]) ----
    for (int idx = tid; idx < 4608; idx += TPB){
        int p = idx / 1152, r = idx % 1152, n = r / PITCH, k = r % PITCH;
        sb[OW1 + idx] = f2tf((k < 17) ? W1[p*544 + k*32 + n] : 0.f);
    }
    for (int idx = tid; idx < 4608; idx += TPB){
        int p = idx / 1152, r = idx % 1152, n = r / PITCH, k = r % PITCH;
        sb[OW2 + idx] = f2tf((k < 32) ? W2[p*1024 + k*32 + n] : 0.f);
    }
    for (int idx = tid; idx < 13824; idx += TPB){
        int g = idx / PITCH, k = idx % PITCH;
        float v = 0.f;
        if (k < 32){
            if (g < 64)       v = W300[k*64  + g];
            else if (g < 128) v = W301[k*64  + (g-64)];
            else if (g < 192) v = W310[k*64  + (g-128)];
            else              v = W311[k*192 + (g-192)];
        }
        sb[OW3 + idx] = f2tf(v);
    }
    for (int i = tid; i < 128; i += TPB){ sb[OB1+i] = b1[i]; sb[OB2+i] = b2[i]; }
    for (int i = tid; i < 384; i += TPB){
        float v;
        if (i < 64) v = b300[i]; else if (i < 128) v = b301[i-64];
        else if (i < 192) v = b310[i-128]; else v = b311[i-192];
        sb[OB3+i] = v;
    }

    // per-thread epilogue mapping: two threads per edge (o-halves)
    const int el   = tid & 127;
    const int half = tid >> 7;
    const int obase = half * 4;

    for (int tile = blockIdx.x; tile < ntiles; tile += gridDim.x){
        __syncthreads();   // Rbuf/EF alias boundary (also orders weight staging, 1st iter)

        // ---- EF tile fill (tf32), rows = edges ----
        if (tid < TILE_E){
            int ge = tile*TILE_E + tid;
            float* row = sb + OEF + tid*PITCH;
            if (ge < E){
                const float4* w4 = (const float4*)(wemb + (size_t)ge*16);
#pragma unroll
                for (int c = 0; c < 4; c++){
                    float4 v = w4[c];
                    row[4*c+0]=f2tf(v.x); row[4*c+1]=f2tf(v.y);
                    row[4*c+2]=f2tf(v.z); row[4*c+3]=f2tf(v.w);
                }
                row[16] = f2tf(radial[ge]);
            } else {
#pragma unroll
                for (int c = 0; c < 17; c++) row[c] = 0.f;
            }
#pragma unroll
            for (int c = 17; c < 24; c++) row[c] = 0.f;
        }
        __syncthreads();

        // ---- radial MLP: 4 pairs, warp-local rows ----
#pragma unroll 1
        for (int p = 0; p < 4; p++){
            // GEMM1: EF[128x24] @ W1p[24x32] -> H (relu + bias)
            float d1[4][4] = {};
            const float* WB1p = sb + OW1 + p*32*PITCH;
#pragma unroll
            for (int k0 = 0; k0 < 24; k0 += 8){
                uint32_t a[4]; lda(a, sb + OEF, r0, k0, q, t);
#pragma unroll
                for (int nt = 0; nt < 4; nt++){
                    uint32_t b[2]; ldb(b, WB1p, nt*8, k0, q, t);
                    mma8(d1[nt], a, b);
                }
            }
            __syncwarp();   // H reads of previous pair done
            {
                float* H = sb + OH;
                const float* bia = sb + OB1 + p*32;
#pragma unroll
                for (int nt = 0; nt < 4; nt++){
                    int c0 = nt*8 + t*2;
                    H[(r0+q)*PITCH   + c0]   = f2tf(fmaxf(d1[nt][0] + bia[c0],   0.f));
                    H[(r0+q)*PITCH   + c0+1] = f2tf(fmaxf(d1[nt][1] + bia[c0+1], 0.f));
                    H[(r0+q+8)*PITCH + c0]   = f2tf(fmaxf(d1[nt][2] + bia[c0],   0.f));
                    H[(r0+q+8)*PITCH + c0+1] = f2tf(fmaxf(d1[nt][3] + bia[c0+1], 0.f));
                }
            }
            __syncwarp();

            // GEMM2: H[128x32] @ W2p[32x32] -> H2[p] (relu + bias)
            float d2[4][4] = {};
            const float* WB2p = sb + OW2 + p*32*PITCH;
#pragma unroll
            for (int k0 = 0; k0 < 32; k0 += 8){
                uint32_t a[4]; lda(a, sb + OH, r0, k0, q, t);
#pragma unroll
                for (int nt = 0; nt < 4; nt++){
                    uint32_t b[2]; ldb(b, WB2p, nt*8, k0, q, t);
                    mma8(d2[nt], a, b);
                }
            }
            {
                float* H2 = sb + OH2 + p*128*PITCH;
                const float* bia = sb + OB2 + p*32;
#pragma unroll
                for (int nt = 0; nt < 4; nt++){
                    int c0 = nt*8 + t*2;
                    H2[(r0+q)*PITCH   + c0]   = f2tf(fmaxf(d2[nt][0] + bia[c0],   0.f));
                    H2[(r0+q)*PITCH   + c0+1] = f2tf(fmaxf(d2[nt][1] + bia[c0+1], 0.f));
                    H2[(r0+q+8)*PITCH + c0]   = f2tf(fmaxf(d2[nt][2] + bia[c0],   0.f));
                    H2[(r0+q+8)*PITCH + c0+1] = f2tf(fmaxf(d2[nt][3] + bia[c0+1], 0.f));
                }
            }
            __syncwarp();
        }

        // ---- GEMM3 chunks + fused epilogue ----
        const int ge  = tile*TILE_E + el;
        const bool act = (ge < E);
        int sN = 0, dN = 0;
        float fs0[8], b00 = 0.f, acc0[4], t_o[4];

        // chunk R00 (pair 0, cols 0..63)
        gemm3_chunk<8>(sb, 0, 0, r0, q, t);
        __syncthreads();
        if (act){
            sN = src[ge]; dN = dst[ge];
            const float4* f04 = (const float4*)(feat0 + (size_t)sN*8);
            float4 v0 = f04[0], v1 = f04[1];
            fs0[0]=v0.x; fs0[1]=v0.y; fs0[2]=v0.z; fs0[3]=v0.w;
            fs0[4]=v1.x; fs0[5]=v1.y; fs0[6]=v1.z; fs0[7]=v1.w;
            b00 = B00g[ge];
            const float* Re = sb + ORB + el*RPITCH;
#pragma unroll
            for (int o = 0; o < 4; o++){
                float m = 0.f;
#pragma unroll
                for (int i = 0; i < 8; i++) m += Re[(obase+o)*8 + i] * fs0[i];
                acc0[o] = b00 * m;
            }
            if (half == 0) atomicAdd(&g_cnt[dN], 1);
        }
        __syncthreads();

        // chunk R10 (pair 2, cols 128..191)
        gemm3_chunk<8>(sb, 2, 128, r0, q, t);
        __syncthreads();
        if (act){
            float B10r[3];
#pragma unroll
            for (int m = 0; m < 3; m++) B10r[m] = B10g[(size_t)ge*3 + m];
            float fs1[24];
            const float4* f14 = (const float4*)(feat1 + (size_t)sN*24);
#pragma unroll
            for (int c = 0; c < 6; c++){
                float4 v = f14[c];
                fs1[4*c]=v.x; fs1[4*c+1]=v.y; fs1[4*c+2]=v.z; fs1[4*c+3]=v.w;
            }
            float g1[8];
#pragma unroll
            for (int i = 0; i < 8; i++)
                g1[i] = B10r[0]*fs1[i*3] + B10r[1]*fs1[i*3+1] + B10r[2]*fs1[i*3+2];
            const float* Re = sb + ORB + el*RPITCH;
            float* outd = out + (size_t)dN*32;
#pragma unroll
            for (int o = 0; o < 4; o++){
                float m = 0.f;
#pragma unroll
                for (int i = 0; i < 8; i++) m += Re[(obase+o)*8 + i] * g1[i];
                atomicAdd(outd + (obase+o)*4, acc0[o] + m);
            }
        }
        __syncthreads();

        // chunk R01 (pair 1, cols 64..127)
        gemm3_chunk<8>(sb, 1, 64, r0, q, t);
        __syncthreads();
        if (act){
            const float* Re = sb + ORB + el*RPITCH;
#pragma unroll
            for (int o = 0; o < 4; o++){
                float m = 0.f;
#pragma unroll
                for (int i = 0; i < 8; i++) m += Re[(obase+o)*8 + i] * fs0[i];
                t_o[o] = m;
            }
        }
        __syncthreads();

        // chunks R11 (pair 3, cols 192.. in 4 x 48)
#pragma unroll 1
        for (int c = 0; c < 4; c++){
            gemm3_chunk<6>(sb, 3, 192 + c*48, r0, q, t);
            __syncthreads();
            int o0 = c*2;
            if (act && ((o0 >> 2) == half)){
                float B01r[3], B11r[27], fs1[24];
#pragma unroll
                for (int m = 0; m < 3; m++) B01r[m] = B01g[(size_t)ge*3 + m];
#pragma unroll
                for (int j = 0; j < 27; j++) B11r[j] = B11g[(size_t)ge*27 + j];
                const float4* f14 = (const float4*)(feat1 + (size_t)sN*24);
#pragma unroll
                for (int cc = 0; cc < 6; cc++){
                    float4 v = f14[cc];
                    fs1[4*cc]=v.x; fs1[4*cc+1]=v.y; fs1[4*cc+2]=v.z; fs1[4*cc+3]=v.w;
                }
                const float* Re = sb + ORB + el*RPITCH;
                float* outd = out + (size_t)dN*32;
#pragma unroll
                for (int oo = 0; oo < 2; oo++){
                    int o = o0 + oo;
                    const float* r3 = Re + oo*24;
                    float S[9] = {};
#pragma unroll
                    for (int i = 0; i < 8; i++){
#pragma unroll
                        for (int f = 0; f < 3; f++){
                            float rv = r3[i*3+f];
                            S[0+f] += rv * fs1[i*3+0];
                            S[3+f] += rv * fs1[i*3+1];
                            S[6+f] += rv * fs1[i*3+2];
                        }
                    }
                    float tt = t_o[o - obase];
#pragma unroll
                    for (int m = 0; m < 3; m++){
                        float acc = B01r[m] * tt;
#pragma unroll
                        for (int n = 0; n < 3; n++)
#pragma unroll
                            for (int f = 0; f < 3; f++)
                                acc += B11r[m*9+n*3+f] * S[n*3+f];
                        atomicAdd(outd + o*4 + 1 + m, acc);
                    }
                }
            }
            __syncthreads();
        }
    }
}

__global__ void __launch_bounds__(TPB)
finalize_kernel(const float* __restrict__ feat0, const float* __restrict__ feat1,
                const float* __restrict__ ws0, const float* __restrict__ ws1,
                float* __restrict__ out, int N)
{
    int n = blockIdx.x * TPB + threadIdx.x;
    if (n >= N) return;
    int c = g_cnt[n];
    float inv = 1.0f / (float)(c > 1 ? c : 1);
    float sf  = (c > 0) ? 1.0f : 0.0f;

    float f0[8], f1[24];
#pragma unroll
    for (int i = 0; i < 8; i++)  f0[i] = feat0[(size_t)n*8 + i] * sf;
#pragma unroll
    for (int j = 0; j < 24; j++) f1[j] = feat1[(size_t)n*24 + j] * sf;

#pragma unroll
    for (int o = 0; o < 8; o++){
        float a0 = 0.f, ax = 0.f, ay = 0.f, az = 0.f;
#pragma unroll
        for (int i = 0; i < 8; i++){
            float w0 = ws0[o*8+i];
            float w1 = ws1[o*8+i];
            a0 += w0 * f0[i];
            ax += w1 * f1[i*3+0];
            ay += w1 * f1[i*3+1];
            az += w1 * f1[i*3+2];
        }
        size_t base = (size_t)n*32 + o*4;
        out[base+0] = out[base+0]*inv + a0;
        out[base+1] = out[base+1]*inv + ax;
        out[base+2] = out[base+2]*inv + ay;
        out[base+3] = out[base+3]*inv + az;
    }
}

extern "C" void kernel_launch(void* const* d_in, const int* in_sizes, int n_in,
                              void* d_out, int out_size)
{
    const int*   src    = (const int*)  d_in[0];
    const int*   dst    = (const int*)  d_in[1];
    const float* feat0  = (const float*)d_in[2];
    const float* feat1  = (const float*)d_in[3];
    const float* wemb   = (const float*)d_in[4];
    const float* radial = (const float*)d_in[5];
    const float* B00    = (const float*)d_in[6];
    const float* B01    = (const float*)d_in[7];
    const float* B10    = (const float*)d_in[8];
    const float* B11    = (const float*)d_in[9];
    const float* W1     = (const float*)d_in[10];
    const float* b1     = (const float*)d_in[11];
    const float* W2     = (const float*)d_in[12];
    const float* b2     = (const float*)d_in[13];
    const float* W300   = (const float*)d_in[14];
    const float* b300   = (const float*)d_in[15];
    const float* W301   = (const float*)d_in[16];
    const float* b301   = (const float*)d_in[17];
    const float* W310   = (const float*)d_in[18];
    const float* b310   = (const float*)d_in[19];
    const float* W311   = (const float*)d_in[20];
    const float* b311   = (const float*)d_in[21];
    const float* ws0    = (const float*)d_in[22];
    const float* ws1    = (const float*)d_in[23];

    const int E = in_sizes[0];
    const int N = in_sizes[2] / 8;
    float* out = (float*)d_out;

    cudaFuncSetAttribute(edge_kernel,
                         cudaFuncAttributeMaxDynamicSharedMemorySize, SMEM_BYTES);

    int total = N * 32;
    zero_kernel<<<(total + TPB - 1) / TPB, TPB>>>(out, total, N);

    int ntiles = (E + TILE_E - 1) / TILE_E;
    int grid = ntiles < 148 ? ntiles : 148;
    edge_kernel<<<grid, TPB, SMEM_BYTES>>>(
        src, dst, feat0, feat1, wemb, radial,
        B00, B01, B10, B11,
        W1, b1, W2, b2,
        W300, b300, W301, b301, W310, b310, W311, b311,
        out, E, ntiles);

    finalize_kernel<<<(N + TPB - 1) / TPB, TPB>>>(feat0, feat1, ws0, ws1, out, N);
}